// round 14
// baseline (speedup 1.0000x reference)
#include <cuda_runtime.h>
#include <math.h>

// GATTrafficPredictionModel — algebraically collapsed (R1 derivation):
//   wh[b,k,h]  = sum_f x[b,11,f] * W_heads[k,f,h]
//   hc[b,m]    = elu(wh)                        (m = k*64+h, 512 values)
//   who[b,c]   = sum_m hc[b,m] * W_out[m,c]
//   out[b,c]   = sum_j who[b,j] * (sum_n Wf[c, n*64+j]) + bf[c]
// (both GAT softmaxes are exactly uniform — all node features are identical —
//  so a1/a2 drop out exactly)
//
// R14: warp-specialized single kernel. 64 blocks x 512 threads, block c:
//   warps 0-7  (tid<256):  phase A — stream Wf row c (128 KB) -> sums[64] (smem)
//   warps 8-15 (tid>=256): phase B — who-half (b,half)=(c>>1,c&1) -> g_whop
// A and B overlap; named barriers sync within each group. Then a 64-arrival
// grid barrier (all 64 CTAs co-resident on 148 SMs -> spin is deadlock-free),
// then phase D: final 32x64 dot for channel c.

#define BB 32
#define FF 128
#define HH 64
#define CC 64
#define NNODE 512
#define GRID 64
#define RP 65   // padded pitch for the 16x64 reduce tile

__device__ float g_whop[BB * 2 * CC];   // who partials: [b][half][c]
__device__ int g_c1 = 0;                // barrier arrivals
__device__ int g_c2 = 0;                // completions (for reset)

#define BAR_A() asm volatile("bar.sync 2, 256;" ::: "memory")
#define BAR_B() asm volatile("bar.sync 1, 256;" ::: "memory")

__global__ __launch_bounds__(512) void fused(
    const float* __restrict__ Wf,
    const float* __restrict__ x,
    const float* __restrict__ W_heads,
    const float* __restrict__ W_out,
    const float* __restrict__ bf,
    float* __restrict__ out) {
  const int tid = threadIdx.x;
  const int c = blockIdx.x;
  const int b = c >> 1;
  const int half = c & 1;

  __shared__ float red[16 * RP];       // Wf reduce tile (A group)
  __shared__ float sums[CC];           // S[c][j] — survives to phase D
  __shared__ float xl[FF];             // x_last (B group)
  __shared__ float hc[256];
  __shared__ float red2[256];
  __shared__ float who_sh[BB * CC];

  if (tid < 256) {
    // ───── Phase A: stream Wf row c, reduce to 64 column sums ─────
    const float4* base = (const float4*)(Wf + (size_t)c * (NNODE * CC));
    float4 a = make_float4(0.f, 0.f, 0.f, 0.f);
#pragma unroll
    for (int i = 0; i < 32; i++) {       // idx = tid + 256*i; (idx&15)==tid&15
      float4 v = base[tid + 256 * i];
      a.x += v.x; a.y += v.y; a.z += v.z; a.w += v.w;
    }
    const int row = tid >> 4;            // 0..15
    const int col = (tid & 15) * 4;      // 0..60
    red[row * RP + col + 0] = a.x;
    red[row * RP + col + 1] = a.y;
    red[row * RP + col + 2] = a.z;
    red[row * RP + col + 3] = a.w;
    BAR_A();
    if (tid < CC) {
      float t = 0.f;
#pragma unroll
      for (int r = 0; r < 16; r++) t += red[r * RP + tid];
      sums[tid] = t;
    }
  } else {
    // ───── Phase B: who-half for (b, half) ─────
    const int t2 = tid - 256;            // 0..255
    if (t2 < FF) xl[t2] = x[(b * 12 + 11) * FF + t2];
    BAR_B();
    {
      const int m = half * 256 + t2;
      const float* w = W_heads + (size_t)(m >> 6) * (FF * HH) + (m & 63);
      float a0 = 0.f, a1 = 0.f;
#pragma unroll
      for (int f = 0; f < FF; f += 2) {
        a0 = fmaf(xl[f], w[f * HH], a0);
        a1 = fmaf(xl[f + 1], w[(f + 1) * HH], a1);
      }
      const float acc = a0 + a1;
      hc[t2] = acc > 0.f ? acc : (__expf(acc) - 1.f);
    }
    BAR_B();
    {
      const int cc = t2 & 63;
      const int part = t2 >> 6;
      float acc = 0.f;
      const float* wo = W_out + (size_t)(half * 256) * CC + cc;
#pragma unroll
      for (int i = 0; i < 64; i++) {
        const int ml = part * 64 + i;
        acc = fmaf(hc[ml], wo[ml * CC], acc);
      }
      red2[t2] = acc;
    }
    BAR_B();
    if (t2 < CC) {
      g_whop[(b * 2 + half) * CC + t2] =
          red2[t2] + red2[t2 + 64] + red2[t2 + 128] + red2[t2 + 192];
    }
  }

  // ───── join groups, grid barrier (64 arrivals, volatile poll) ─────
  __syncthreads();
  if (tid == 0) {
    __threadfence();
    atomicAdd(&g_c1, 1);
    while (*(volatile int*)&g_c1 < GRID) { }
    const int d = atomicAdd(&g_c2, 1);   // last one through resets counters
    if (d == GRID - 1) {
      atomicExch(&g_c1, 0);
      atomicExch(&g_c2, 0);
    }
  }
  __syncthreads();
  __threadfence();

  // ───── Phase D: combine who halves + final dot for channel c ─────
  for (int i = tid; i < BB * CC; i += 512) {
    const int b2 = i >> 6, cc = i & 63;
    who_sh[i] = g_whop[b2 * 128 + cc] + g_whop[b2 * 128 + 64 + cc];
  }
  __syncthreads();

  if (tid < BB) {
    float acc = bf[c];
    const float* w = who_sh + tid * CC;
#pragma unroll
    for (int j = 0; j < CC; j++) acc = fmaf(w[j], sums[j], acc);
    out[tid * CC + c] = acc;
  }
}

extern "C" void kernel_launch(void* const* d_in, const int* in_sizes, int n_in,
                              void* d_out, int out_size) {
  const float* x       = (const float*)d_in[0];
  const float* W_heads = (const float*)d_in[1];
  const float* W_out   = (const float*)d_in[4];
  const float* Wf      = (const float*)d_in[7];
  const float* bf      = (const float*)d_in[8];
  float* out = (float*)d_out;

  fused<<<GRID, 512>>>(Wf, x, W_heads, W_out, bf, out);
}

// round 17
// speedup vs baseline: 1.1910x; 1.1910x over previous
#include <cuda_runtime.h>
#include <math.h>

// GATTrafficPredictionModel — algebraically collapsed (R1 derivation):
//   wh[b,k,h]  = sum_f x[b,11,f] * W_heads[k,f,h]
//   hc[b,m]    = elu(wh)                        (m = k*64+h, 512 values)
//   who[b,c]   = sum_m hc[b,m] * W_out[m,c]
//   out[b,c]   = sum_j who[b,j] * (sum_n Wf[c, n*64+j]) + bf[c]
// (both GAT softmaxes are exactly uniform — all node features identical —
//  so a1/a2 drop out exactly)
//
// R15: 128 blocks x 512 threads, all co-resident (<=148 SMs) -> grid spin safe.
//  every block:  phase A — stream 64 KB half-row of Wf (8 float4/thread, one
//                latency exposure) -> column partials in g_part[bx][64]
//  blocks >=64:  phase B — who-half (b,half); f-split over 512 threads
//                (64-deep chains); A loads issued BEFORE B, consumed after.
//  grid barrier (128 arrivals, volatile poll, self-resetting)
//  blocks <64:   phase D — sums = g_part[2c]+g_part[2c+1]; final 32x64 dot.

#define BB 32
#define FF 128
#define HH 64
#define CC 64
#define NNODE 512
#define GRID 128
#define RP 65   // padded pitch for the 32x64 reduce tile

__device__ float g_whop[BB * 2 * CC];   // who partials: [b][half][c]
__device__ float g_part[GRID * CC];     // Wf col partials: [bx][j]
__device__ int g_c1 = 0;                // barrier arrivals
__device__ int g_c2 = 0;                // completions (reset)

__global__ __launch_bounds__(512) void fused(
    const float* __restrict__ Wf,
    const float* __restrict__ x,
    const float* __restrict__ W_heads,
    const float* __restrict__ W_out,
    const float* __restrict__ bf,
    float* __restrict__ out) {
  const int tid = threadIdx.x;
  const int bx = blockIdx.x;
  const int arow = bx >> 1;            // Wf row for phase A
  const int ahalf = bx & 1;            // which 16384-float half

  __shared__ float red[32 * RP];
  __shared__ float xl[FF];
  __shared__ float bpart[512];
  __shared__ float hc[256];
  __shared__ float red2[512];
  __shared__ float sums[CC];
  __shared__ float who_sh[BB * CC];

  // ── Phase A (issue): 8 independent float4 loads, all in flight ──
  const float4* base = (const float4*)(Wf + (size_t)arow * (NNODE * CC) +
                                       (size_t)ahalf * (NNODE * CC / 2));
  float4 v0 = base[tid];
  float4 v1 = base[tid + 512];
  float4 v2 = base[tid + 1024];
  float4 v3 = base[tid + 1536];
  float4 v4 = base[tid + 2048];
  float4 v5 = base[tid + 2560];
  float4 v6 = base[tid + 3072];
  float4 v7 = base[tid + 3584];

  // ── Phase B (blocks >= 64): who-half, overlapped with A's latency ──
  if (bx >= 64) {
    const int idx = bx - 64;           // 0..63
    const int b = idx >> 1;
    const int half = idx & 1;

    if (tid < FF) xl[tid] = x[(b * 12 + 11) * FF + tid];
    __syncthreads();

    {  // wh dot, f-split: thread = (m within half, f-half)
      const int mm = tid & 255;
      const int fh = tid >> 8;         // 0/1
      const int m = half * 256 + mm;
      const float* w =
          W_heads + (size_t)(m >> 6) * (FF * HH) + (m & 63) + (size_t)fh * 64 * HH;
      const float* xp = xl + fh * 64;
      float b0 = 0.f, b1 = 0.f, b2 = 0.f, b3 = 0.f;
#pragma unroll
      for (int f = 0; f < 64; f += 4) {
        b0 = fmaf(xp[f + 0], w[(f + 0) * HH], b0);
        b1 = fmaf(xp[f + 1], w[(f + 1) * HH], b1);
        b2 = fmaf(xp[f + 2], w[(f + 2) * HH], b2);
        b3 = fmaf(xp[f + 3], w[(f + 3) * HH], b3);
      }
      bpart[tid] = (b0 + b1) + (b2 + b3);
    }
    __syncthreads();
    if (tid < 256) {
      const float acc = bpart[tid] + bpart[tid + 256];
      hc[tid] = acc > 0.f ? acc : (__expf(acc) - 1.f);
    }
    __syncthreads();
    {  // who partial: 8-way split over the 256 m's
      const int cc = tid & 63;
      const int part = tid >> 6;       // 0..7
      const float* wo = W_out + (size_t)(half * 256) * CC + cc;
      float acc = 0.f;
#pragma unroll
      for (int i = 0; i < 32; i++) {
        const int ml = part * 32 + i;
        acc = fmaf(hc[ml], wo[ml * CC], acc);
      }
      red2[tid] = acc;
    }
    __syncthreads();
    if (tid < CC) {
      float t = 0.f;
#pragma unroll
      for (int p = 0; p < 8; p++) t += red2[tid + 64 * p];
      g_whop[(b * 2 + half) * CC + tid] = t;
    }
  }

  // ── Phase A (consume): tree-sum, reduce tile, write partials ──
  {
    float ax = ((v0.x + v1.x) + (v2.x + v3.x)) + ((v4.x + v5.x) + (v6.x + v7.x));
    float ay = ((v0.y + v1.y) + (v2.y + v3.y)) + ((v4.y + v5.y) + (v6.y + v7.y));
    float az = ((v0.z + v1.z) + (v2.z + v3.z)) + ((v4.z + v5.z) + (v6.z + v7.z));
    float aw = ((v0.w + v1.w) + (v2.w + v3.w)) + ((v4.w + v5.w) + (v6.w + v7.w));
    const int row = tid >> 4;          // 0..31
    const int col = (tid & 15) * 4;    // (idx&15) invariant across the 8 loads
    red[row * RP + col + 0] = ax;
    red[row * RP + col + 1] = ay;
    red[row * RP + col + 2] = az;
    red[row * RP + col + 3] = aw;
  }
  __syncthreads();
  if (tid < CC) {
    float t = 0.f;
#pragma unroll
    for (int r = 0; r < 32; r++) t += red[r * RP + tid];
    g_part[bx * CC + tid] = t;
  }

  // ── Grid barrier: 128 arrivals, volatile poll, self-reset ──
  __syncthreads();
  if (tid == 0) {
    __threadfence();
    atomicAdd(&g_c1, 1);
    while (*(volatile int*)&g_c1 < GRID) { }
    const int d = atomicAdd(&g_c2, 1);
    if (d == GRID - 1) {
      atomicExch(&g_c1, 0);
      atomicExch(&g_c2, 0);
    }
  }
  __syncthreads();
  __threadfence();

  if (bx >= 64) return;

  // ── Phase D (blocks < 64): channel c = bx ──
  const int c = bx;
  if (tid < CC) sums[tid] = g_part[(2 * c) * CC + tid] + g_part[(2 * c + 1) * CC + tid];
  for (int i = tid; i < BB * CC; i += 512) {
    const int b2 = i >> 6, cc = i & 63;
    who_sh[i] = g_whop[b2 * 128 + cc] + g_whop[b2 * 128 + 64 + cc];
  }
  __syncthreads();

  if (tid < BB) {
    float acc = bf[c];
    const float* w = who_sh + tid * CC;
#pragma unroll
    for (int j = 0; j < CC; j++) acc = fmaf(w[j], sums[j], acc);
    out[tid * CC + c] = acc;
  }
}

extern "C" void kernel_launch(void* const* d_in, const int* in_sizes, int n_in,
                              void* d_out, int out_size) {
  const float* x       = (const float*)d_in[0];
  const float* W_heads = (const float*)d_in[1];
  const float* W_out   = (const float*)d_in[4];
  const float* Wf      = (const float*)d_in[7];
  const float* bf      = (const float*)d_in[8];
  float* out = (float*)d_out;

  fused<<<GRID, 512>>>(Wf, x, W_heads, W_out, bf, out);
}